// round 9
// baseline (speedup 1.0000x reference)
#include <cuda_runtime.h>
#include <cuda_bf16.h>

// FPN RoIAlign: 5 levels (p2..p6, hw 256..16), NHWC fp32, C=256.
// B=2, R=512, OUT=7x7, sr=2.
// Decomposition: 4096 CTAs of 64 threads — one CTA per (box, bin-group).
// Group g covers bins {g, g+4, ...} (13 or 12 bins). Each thread owns 4
// consecutive channels (float4); a corner gather is a 1KB coalesced
// wavefront across the CTA. Single-wave launch (4096 < 32 CTA/SM * 148),
// no wave-quantization tail.

#define RR 512
#define MAXB 13          // max bins per group
#define MAXS (MAXB * 4)  // max subsamples per group

struct Geo {
    int4   off;   // byte offsets of the 4 bilinear corners (incl. batch base)
    float4 wt;    // matching bilinear weights (0 if sample invalid)
};

__global__ __launch_bounds__(64) void roi_align_fpn_kernel(
    const float* __restrict__ p2, const float* __restrict__ p3,
    const float* __restrict__ p4, const float* __restrict__ p5,
    const float* __restrict__ p6, const float* __restrict__ prop,
    float* __restrict__ out)
{
    const int group = blockIdx.x;   // 0..3: bin subset
    const int r     = blockIdx.y;
    const int bimg  = blockIdx.z;
    const int tid   = threadIdx.x;  // 0..63 = float4 channel index

    const int nbins = (group == 0) ? 13 : 12;

    // Box in image coords
    const float4 box = reinterpret_cast<const float4*>(prop)[bimg * RR + r];

    // Level assignment: lvl = clip(floor(4 + log2(sqrt(w*h)/224)), 2, 6)
    float bwd = fmaxf(box.z - box.x, 1.0f);
    float bhd = fmaxf(box.w - box.y, 1.0f);
    float lvlf = floorf(4.0f + log2f(sqrtf(bwd * bhd) * (1.0f / 224.0f)));
    int lvl = (int)fminf(fmaxf(lvlf, 2.0f), 6.0f);

    const float* __restrict__ f;
    int H;
    switch (lvl) {
        case 2:  f = p2; H = 256; break;
        case 3:  f = p3; H = 128; break;
        case 4:  f = p4; H = 64;  break;
        case 5:  f = p5; H = 32;  break;
        default: f = p6; H = 16;  break;
    }
    const float scale = 1.0f / (float)(1 << lvl);

    const float x1 = box.x * scale;
    const float y1 = box.y * scale;
    const float roi_w = fmaxf(box.z * scale - x1, 1.0f);
    const float roi_h = fmaxf(box.w * scale - y1, 1.0f);
    const float bin_w = roi_w * (1.0f / 7.0f);
    const float bin_h = roi_h * (1.0f / 7.0f);

    __shared__ Geo s_geo[MAXS];

    // Geometry for this group's subsamples: local bin lb -> global bin g+4*lb.
    if (tid < nbins * 4) {
        const int lb = tid >> 2;
        const int s  = tid & 3;
        const int sx = s & 1;
        const int sy = s >> 1;
        const int bin = group + 4 * lb;
        const int ow = bin % 7;
        const int oh = bin / 7;

        const float fh = (float)H;
        float Y = y1 + ((float)oh + ((float)sy + 0.5f) * 0.5f) * bin_h;
        float X = x1 + ((float)ow + ((float)sx + 0.5f) * 0.5f) * bin_w;

        bool valid = (Y >= -1.0f) && (Y <= fh) && (X >= -1.0f) && (X <= fh);

        float y = fminf(fmaxf(Y, 0.0f), fh - 1.0f);
        float x = fminf(fmaxf(X, 0.0f), fh - 1.0f);
        float y0 = floorf(y);
        float x0 = floorf(x);
        int y0i = (int)y0;
        int x0i = (int)x0;
        int y1i = min(y0i + 1, H - 1);
        int x1i = min(x0i + 1, H - 1);
        float ly = y - y0, lx = x - x0;
        float hy = 1.0f - ly, hx = 1.0f - lx;
        float v = valid ? 1.0f : 0.0f;

        // byte offsets: pixel row = 256 floats = 1024 bytes
        const int base = bimg * H * H * 1024;
        Geo g;
        g.off.x = base + (y0i * H + x0i) * 1024;
        g.off.y = base + (y0i * H + x1i) * 1024;
        g.off.z = base + (y1i * H + x0i) * 1024;
        g.off.w = base + (y1i * H + x1i) * 1024;
        g.wt.x = hy * hx * v;
        g.wt.y = hy * lx * v;
        g.wt.z = ly * hx * v;
        g.wt.w = ly * lx * v;
        s_geo[tid] = g;
    }
    __syncthreads();

    // per-thread channel base in bytes
    const char* __restrict__ fb = reinterpret_cast<const char*>(f) + tid * 16;
    float4* __restrict__ o4 = reinterpret_cast<float4*>(out)
                            + ((size_t)(bimg * RR + r) * 49) * 64 + tid;

    for (int lb = 0; lb < nbins; ++lb) {
        const int bin = group + 4 * lb;
        float4 acc = make_float4(0.f, 0.f, 0.f, 0.f);
        // Two half-bin batches: 2 subsamples (8 corner loads, MLP=8) each.
        #pragma unroll
        for (int half = 0; half < 2; ++half) {
            const Geo g0 = s_geo[lb * 4 + half * 2 + 0];
            const Geo g1 = s_geo[lb * 4 + half * 2 + 1];
            float4 v0 = __ldg((const float4*)(fb + g0.off.x));
            float4 v1 = __ldg((const float4*)(fb + g0.off.y));
            float4 v2 = __ldg((const float4*)(fb + g0.off.z));
            float4 v3 = __ldg((const float4*)(fb + g0.off.w));
            float4 v4 = __ldg((const float4*)(fb + g1.off.x));
            float4 v5 = __ldg((const float4*)(fb + g1.off.y));
            float4 v6 = __ldg((const float4*)(fb + g1.off.z));
            float4 v7 = __ldg((const float4*)(fb + g1.off.w));
            acc.x += g0.wt.x * v0.x; acc.y += g0.wt.x * v0.y; acc.z += g0.wt.x * v0.z; acc.w += g0.wt.x * v0.w;
            acc.x += g0.wt.y * v1.x; acc.y += g0.wt.y * v1.y; acc.z += g0.wt.y * v1.z; acc.w += g0.wt.y * v1.w;
            acc.x += g0.wt.z * v2.x; acc.y += g0.wt.z * v2.y; acc.z += g0.wt.z * v2.z; acc.w += g0.wt.z * v2.w;
            acc.x += g0.wt.w * v3.x; acc.y += g0.wt.w * v3.y; acc.z += g0.wt.w * v3.z; acc.w += g0.wt.w * v3.w;
            acc.x += g1.wt.x * v4.x; acc.y += g1.wt.x * v4.y; acc.z += g1.wt.x * v4.z; acc.w += g1.wt.x * v4.w;
            acc.x += g1.wt.y * v5.x; acc.y += g1.wt.y * v5.y; acc.z += g1.wt.y * v5.z; acc.w += g1.wt.y * v5.w;
            acc.x += g1.wt.z * v6.x; acc.y += g1.wt.z * v6.y; acc.z += g1.wt.z * v6.z; acc.w += g1.wt.z * v6.w;
            acc.x += g1.wt.w * v7.x; acc.y += g1.wt.w * v7.y; acc.z += g1.wt.w * v7.z; acc.w += g1.wt.w * v7.w;
        }
        acc.x *= 0.25f; acc.y *= 0.25f; acc.z *= 0.25f; acc.w *= 0.25f;
        __stcs(o4 + (size_t)bin * 64, acc);   // streaming store: keep L2 for features
    }
}

extern "C" void kernel_launch(void* const* d_in, const int* in_sizes, int n_in,
                              void* d_out, int out_size) {
    // hw = 1024/stride: p2=256, p3=128, p4=64, p5=32, p6=16; C=256, B=2.
    const float *p2 = nullptr, *p3 = nullptr, *p4 = nullptr,
                *p5 = nullptr, *p6 = nullptr, *prop = nullptr;
    for (int i = 0; i < n_in; ++i) {
        switch (in_sizes[i]) {
            case 33554432:  p2   = (const float*)d_in[i]; break; // 2*256*256*256
            case 8388608:   p3   = (const float*)d_in[i]; break; // 2*128*128*256
            case 2097152:   p4   = (const float*)d_in[i]; break; // 2*64*64*256
            case 524288:    p5   = (const float*)d_in[i]; break; // 2*32*32*256
            case 131072:    p6   = (const float*)d_in[i]; break; // 2*16*16*256
            case 4096:      prop = (const float*)d_in[i]; break; // 2*512*4
        }
    }
    dim3 grid(4, RR, 2);   // (bin-group, box, image) = 4096 CTAs of 64 threads
    roi_align_fpn_kernel<<<grid, 64>>>(p2, p3, p4, p5, p6, prop, (float*)d_out);
}

// round 13
// speedup vs baseline: 1.3935x; 1.3935x over previous
#include <cuda_runtime.h>
#include <cuda_bf16.h>

// FPN RoIAlign: 5 levels (p2..p6, hw 256..16), NHWC fp32, C=256.
// B=2, R=512, OUT=7x7, sr=2.
// Grid 2048 = (half, box, image); 256 threads = 4 groups x 64.
// Group g in CTA-half h covers bins with bin % 8 == h*4+g (7 or 6 bins).
// Each thread owns 4 consecutive channels (float4) -> corner gathers are
// 1KB coalesced wavefronts. 5 CTAs/SM -> 740 concurrent; 2048/740 = 2.77
// waves (last 77% full) vs 2 hard waves at grid 1024.

#define RR 512

struct Geo {
    int4   off;   // byte offsets of the 4 bilinear corners (incl. batch base)
    float4 wt;    // matching bilinear weights (0 if sample invalid)
};

__global__ __launch_bounds__(256, 5) void roi_align_fpn_kernel(
    const float* __restrict__ p2, const float* __restrict__ p3,
    const float* __restrict__ p4, const float* __restrict__ p5,
    const float* __restrict__ p6, const float* __restrict__ prop,
    float* __restrict__ out)
{
    const int half = blockIdx.x;    // 0..1
    const int r    = blockIdx.y;
    const int bimg = blockIdx.z;
    const int tid  = threadIdx.x;

    // Box in image coords
    const float4 box = reinterpret_cast<const float4*>(prop)[bimg * RR + r];

    // Level assignment: lvl = clip(floor(4 + log2(sqrt(w*h)/224)), 2, 6)
    float bwd = fmaxf(box.z - box.x, 1.0f);
    float bhd = fmaxf(box.w - box.y, 1.0f);
    float lvlf = floorf(4.0f + log2f(sqrtf(bwd * bhd) * (1.0f / 224.0f)));
    int lvl = (int)fminf(fmaxf(lvlf, 2.0f), 6.0f);

    const float* __restrict__ f;
    int H;
    switch (lvl) {
        case 2:  f = p2; H = 256; break;
        case 3:  f = p3; H = 128; break;
        case 4:  f = p4; H = 64;  break;
        case 5:  f = p5; H = 32;  break;
        default: f = p6; H = 16;  break;
    }
    const float scale = 1.0f / (float)(1 << lvl);

    const float x1 = box.x * scale;
    const float y1 = box.y * scale;
    const float roi_w = fmaxf(box.z * scale - x1, 1.0f);
    const float roi_h = fmaxf(box.w * scale - y1, 1.0f);
    const float bin_w = roi_w * (1.0f / 7.0f);
    const float bin_h = roi_h * (1.0f / 7.0f);

    // s_geo[group][lb][s]: 4 groups x up to 7 local bins x 4 subsamples.
    __shared__ Geo s_geo[4 * 7 * 4];

    if (tid < 112) {
        const int group = tid / 28;
        const int rem   = tid % 28;
        const int lb    = rem >> 2;
        const int s     = rem & 3;
        const int sub   = half * 4 + group;     // bin % 8 class
        const int bin   = sub + 8 * lb;
        if (bin < 49) {
            const int sx = s & 1;
            const int sy = s >> 1;
            const int ow = bin % 7;
            const int oh = bin / 7;

            const float fh = (float)H;
            float Y = y1 + ((float)oh + ((float)sy + 0.5f) * 0.5f) * bin_h;
            float X = x1 + ((float)ow + ((float)sx + 0.5f) * 0.5f) * bin_w;

            bool valid = (Y >= -1.0f) && (Y <= fh) && (X >= -1.0f) && (X <= fh);

            float y = fminf(fmaxf(Y, 0.0f), fh - 1.0f);
            float x = fminf(fmaxf(X, 0.0f), fh - 1.0f);
            float y0 = floorf(y);
            float x0 = floorf(x);
            int y0i = (int)y0;
            int x0i = (int)x0;
            int y1i = min(y0i + 1, H - 1);
            int x1i = min(x0i + 1, H - 1);
            float ly = y - y0, lx = x - x0;
            float hy = 1.0f - ly, hx = 1.0f - lx;
            float v = valid ? 1.0f : 0.0f;

            // byte offsets: pixel row = 256 floats = 1024 bytes
            const int base = bimg * H * H * 1024;
            Geo g;
            g.off.x = base + (y0i * H + x0i) * 1024;
            g.off.y = base + (y0i * H + x1i) * 1024;
            g.off.z = base + (y1i * H + x0i) * 1024;
            g.off.w = base + (y1i * H + x1i) * 1024;
            g.wt.x = hy * hx * v;
            g.wt.y = hy * lx * v;
            g.wt.z = ly * hx * v;
            g.wt.w = ly * lx * v;
            s_geo[tid] = g;
        }
    }
    __syncthreads();

    const int group = tid >> 6;       // 0..3
    const int c4    = tid & 63;       // float4 channel index
    const int sub   = half * 4 + group;
    const int nbins = (sub == 0) ? 7 : 6;

    const char* __restrict__ fb = reinterpret_cast<const char*>(f) + c4 * 16;
    float4* __restrict__ o4 = reinterpret_cast<float4*>(out)
                            + ((size_t)(bimg * RR + r) * 49) * 64 + c4;
    const Geo* __restrict__ gbase = &s_geo[group * 28];

    for (int lb = 0; lb < nbins; ++lb) {
        const int bin = sub + 8 * lb;
        float4 acc = make_float4(0.f, 0.f, 0.f, 0.f);
        #pragma unroll
        for (int hh = 0; hh < 2; ++hh) {
            const Geo g0 = gbase[lb * 4 + hh * 2 + 0];
            const Geo g1 = gbase[lb * 4 + hh * 2 + 1];
            float4 v0 = __ldg((const float4*)(fb + g0.off.x));
            float4 v1 = __ldg((const float4*)(fb + g0.off.y));
            float4 v2 = __ldg((const float4*)(fb + g0.off.z));
            float4 v3 = __ldg((const float4*)(fb + g0.off.w));
            float4 v4 = __ldg((const float4*)(fb + g1.off.x));
            float4 v5 = __ldg((const float4*)(fb + g1.off.y));
            float4 v6 = __ldg((const float4*)(fb + g1.off.z));
            float4 v7 = __ldg((const float4*)(fb + g1.off.w));
            acc.x += g0.wt.x * v0.x; acc.y += g0.wt.x * v0.y; acc.z += g0.wt.x * v0.z; acc.w += g0.wt.x * v0.w;
            acc.x += g0.wt.y * v1.x; acc.y += g0.wt.y * v1.y; acc.z += g0.wt.y * v1.z; acc.w += g0.wt.y * v1.w;
            acc.x += g0.wt.z * v2.x; acc.y += g0.wt.z * v2.y; acc.z += g0.wt.z * v2.z; acc.w += g0.wt.z * v2.w;
            acc.x += g0.wt.w * v3.x; acc.y += g0.wt.w * v3.y; acc.z += g0.wt.w * v3.z; acc.w += g0.wt.w * v3.w;
            acc.x += g1.wt.x * v4.x; acc.y += g1.wt.x * v4.y; acc.z += g1.wt.x * v4.z; acc.w += g1.wt.x * v4.w;
            acc.x += g1.wt.y * v5.x; acc.y += g1.wt.y * v5.y; acc.z += g1.wt.y * v5.z; acc.w += g1.wt.y * v5.w;
            acc.x += g1.wt.z * v6.x; acc.y += g1.wt.z * v6.y; acc.z += g1.wt.z * v6.z; acc.w += g1.wt.z * v6.w;
            acc.x += g1.wt.w * v7.x; acc.y += g1.wt.w * v7.y; acc.z += g1.wt.w * v7.z; acc.w += g1.wt.w * v7.w;
        }
        acc.x *= 0.25f; acc.y *= 0.25f; acc.z *= 0.25f; acc.w *= 0.25f;
        __stcs(o4 + (size_t)bin * 64, acc);   // streaming store: keep L2 for features
    }
}

extern "C" void kernel_launch(void* const* d_in, const int* in_sizes, int n_in,
                              void* d_out, int out_size) {
    // hw = 1024/stride: p2=256, p3=128, p4=64, p5=32, p6=16; C=256, B=2.
    const float *p2 = nullptr, *p3 = nullptr, *p4 = nullptr,
                *p5 = nullptr, *p6 = nullptr, *prop = nullptr;
    for (int i = 0; i < n_in; ++i) {
        switch (in_sizes[i]) {
            case 33554432:  p2   = (const float*)d_in[i]; break; // 2*256*256*256
            case 8388608:   p3   = (const float*)d_in[i]; break; // 2*128*128*256
            case 2097152:   p4   = (const float*)d_in[i]; break; // 2*64*64*256
            case 524288:    p5   = (const float*)d_in[i]; break; // 2*32*32*256
            case 131072:    p6   = (const float*)d_in[i]; break; // 2*16*16*256
            case 4096:      prop = (const float*)d_in[i]; break; // 2*512*4
        }
    }
    dim3 grid(2, RR, 2);   // (half, box, image) = 2048 CTAs of 256 threads
    roi_align_fpn_kernel<<<grid, 256>>>(p2, p3, p4, p5, p6, prop, (float*)d_out);
}